// round 13
// baseline (speedup 1.0000x reference)
#include <cuda_runtime.h>
#include <cuda_fp16.h>
#include <cstdint>
#include <cstddef>

// ---------------------------------------------------------------------------
// MinGRU (2 layers): tohalf(x,W0,W1) -> GEMM0 -> scan0 -> GEMM1 -> scan1
// B=8, S=4096, D=H=1024, E=2H=2048, M=32768, K=1024.
// GEMM: fp16 mma.sync.m16n8k16 (f32 accum), CTA 128x128 / 4 warps (64x64 each),
//       BK=64, 3-stage cp.async, ldmatrix + xor swizzle, 2 CTAs/SM.
//       Both layers use the same token-major A path (no trans-ldmatrix).
//       Epilogue: stmatrix.x4.trans -> [e][m] smem image -> coalesced STG.128.
// GEMM out: channel-major (B,2H,S) FP16. Scans: warp/channel single-pass
//       affine scan; BOTH emit token-major via smem transpose:
//       scan0 -> half (B,S,H) feeding GEMM1; scan1 -> f32 (B,S,H) output.
// ---------------------------------------------------------------------------

#define B_ 8
#define S_ 4096
#define K_ 1024
#define H_ 1024
#define E_ 2048
#define M_ (B_ * S_)

// scratch (no cudaMalloc allowed)
__device__ __half g_gbuf[(size_t)B_ * E_ * S_];    // 134 MB GEMM out (B,2H,S) half
__device__ __half g_h1h[(size_t)M_ * H_];          // 67 MB layer-0 h, half (B,S,H)
__device__ __half g_xh[(size_t)M_ * K_];           // 67 MB x in half
__device__ __half g_w0h[(size_t)E_ * K_];          // 4 MB
__device__ __half g_w1h[(size_t)E_ * K_];          // 4 MB

// ------------------------------ helpers ------------------------------------

__device__ __forceinline__ void cpasync16(uint32_t dst, const void* src) {
    asm volatile("cp.async.cg.shared.global [%0], [%1], 16;\n" ::"r"(dst), "l"(src));
}
__device__ __forceinline__ void cpcommit() { asm volatile("cp.async.commit_group;\n"); }
__device__ __forceinline__ void cpwait1() { asm volatile("cp.async.wait_group 1;\n"); }
__device__ __forceinline__ void cpwait0() { asm volatile("cp.async.wait_group 0;\n"); }

__device__ __forceinline__ void ldsm4(uint32_t* d, uint32_t addr) {
    asm volatile("ldmatrix.sync.aligned.m8n8.x4.shared.b16 {%0,%1,%2,%3}, [%4];"
                 : "=r"(d[0]), "=r"(d[1]), "=r"(d[2]), "=r"(d[3]) : "r"(addr));
}
__device__ __forceinline__ void stsm4t(uint32_t addr, uint32_t r0, uint32_t r1,
                                       uint32_t r2, uint32_t r3) {
    asm volatile("stmatrix.sync.aligned.m8n8.x4.trans.shared.b16 [%0], {%1,%2,%3,%4};"
                 ::"r"(addr), "r"(r0), "r"(r1), "r"(r2), "r"(r3) : "memory");
}
__device__ __forceinline__ void mma_f16(float* c, const uint32_t* a, const uint32_t* b) {
    asm volatile(
        "mma.sync.aligned.m16n8k16.row.col.f32.f16.f16.f32 "
        "{%0,%1,%2,%3}, {%4,%5,%6,%7}, {%8,%9}, {%0,%1,%2,%3};\n"
        : "+f"(c[0]), "+f"(c[1]), "+f"(c[2]), "+f"(c[3])
        : "r"(a[0]), "r"(a[1]), "r"(a[2]), "r"(a[3]), "r"(b[0]), "r"(b[1]));
}
__device__ __forceinline__ uint32_t packh2(float a, float b) {
    const __half2 h = __floats2half2_rn(a, b);
    return *(const uint32_t*)&h;
}

// --------------------------- f32 -> f16 transform --------------------------

__global__ void tohalf_kernel(const float* __restrict__ in, __half* __restrict__ out) {
    const size_t i = ((size_t)blockIdx.x * 256 + threadIdx.x) * 4;
    const float4 v = *(const float4*)(in + i);
    uint2 u;
    u.x = packh2(v.x, v.y);
    u.y = packh2(v.z, v.w);
    *(uint2*)(out + i) = u;
}

// ------------------------------- GEMM --------------------------------------
// CTA 128(M) x 128(N), BK=64; 4 warps (2x2), warp tile 64x64; 2 CTAs/SM.
// A token-major (M,K) half for BOTH layers. smem: 3 stages x (16+16)KB = 96KB.
// Swizzle: 16B chunk c of row r stored at chunk c ^ (r & 7).

#define BM 128
#define BN 128
#define BK 64
#define NTT (K_ / BK)      // 16 k-tiles
#define ASTG 16384
#define WSTG 16384
#define SMEM_GEMM (3 * (ASTG + WSTG))   // 98304 B
#define SEP 136            // epilogue [e][m] row stride in halfs (272 B)

__global__ __launch_bounds__(128, 2) void gemm_kernel(
    const __half* __restrict__ A, const __half* __restrict__ W,
    const float* __restrict__ bias, __half* __restrict__ Cout)
{
    extern __shared__ char smem[];
    const uint32_t sb = (uint32_t)__cvta_generic_to_shared(smem);

    const int tid = threadIdx.x;
    const int warp = tid >> 5, lane = tid & 31;
    const int tt = lane >> 3, r = lane & 7;   // ldmatrix tile id / row-in-tile
    const int mw = (warp & 1) * 64;
    const int nw = (warp >> 1) * 64;

    const int m0 = blockIdx.y * BM;
    const int b = m0 >> 12;
    const int s0 = m0 & (S_ - 1);
    const int e0 = blockIdx.x * BN;

    const __half* Ablk = A + (size_t)m0 * K_;   // + m_local*K_ + k
    const __half* Wblk = W + (size_t)e0 * K_;

    auto loadTile = [&](int kt, int st) {
        const uint32_t aBase = sb + st * ASTG;
        const uint32_t wBase = sb + 3 * ASTG + st * WSTG;
#pragma unroll
        for (int it = 0; it < 8; ++it) {            // A: 1024 x 16B
            const int id = tid + it * 128;
            const int m = id >> 3, c = id & 7;      // 128 m-rows x 8 chunks
            cpasync16(aBase + m * 128 + ((c ^ (m & 7)) * 16),
                      Ablk + (size_t)m * K_ + kt * BK + c * 8);
        }
#pragma unroll
        for (int it = 0; it < 8; ++it) {            // W: 1024 x 16B
            const int id = tid + it * 128;
            const int e = id >> 3, c = id & 7;
            cpasync16(wBase + e * 128 + ((c ^ (e & 7)) * 16),
                      Wblk + (size_t)e * K_ + kt * BK + c * 8);
        }
    };

    float acc[4][8][4];
#pragma unroll
    for (int i = 0; i < 4; i++)
#pragma unroll
        for (int j = 0; j < 8; j++)
#pragma unroll
            for (int x = 0; x < 4; x++) acc[i][j][x] = 0.f;

    loadTile(0, 0); cpcommit();
    loadTile(1, 1); cpcommit();

    for (int t = 0; t < NTT; ++t) {
        if (t + 1 < NTT) cpwait1(); else cpwait0();   // tile t fully landed
        __syncthreads();
        if (t + 2 < NTT) { loadTile(t + 2, (t + 2) % 3); cpcommit(); }

        const uint32_t aB = sb + (t % 3) * ASTG;
        const uint32_t wB = sb + 3 * ASTG + (t % 3) * WSTG;

#pragma unroll
        for (int s = 0; s < 4; ++s) {               // 4 x k16 per tile
            uint32_t af[4][4], bf[4][4];
#pragma unroll
            for (int i = 0; i < 4; i++) {
                const int row = mw + i * 16 + (tt & 1) * 8 + r;
                const int kch = s * 2 + (tt >> 1);
                ldsm4(af[i], aB + row * 128 + ((kch ^ r) * 16));
            }
#pragma unroll
            for (int jp = 0; jp < 4; jp++) {
                const int e = nw + jp * 16 + (tt >> 1) * 8 + r;
                const int kch = s * 2 + (tt & 1);
                ldsm4(bf[jp], wB + e * 128 + ((kch ^ r) * 16));
            }
#pragma unroll
            for (int i = 0; i < 4; i++)
#pragma unroll
                for (int j = 0; j < 8; j++)
                    mma_f16(acc[i][j], af[i], &bf[j >> 1][(j & 1) * 2]);
        }
    }

    // ---- epilogue: stmatrix.x4.trans -> [e][m] smem image -> STG.128 ----
    __syncthreads();   // mainloop smem stages no longer needed; reuse for image
    {
        const int q = lane & 3;
#pragma unroll
        for (int i = 0; i < 4; i++) {
            const int m0c = mw + i * 16;
#pragma unroll
            for (int jp = 0; jp < 4; jp++) {
                const int eloc = nw + jp * 16;
                const float bv0 = __ldg(bias + e0 + eloc + q * 2);
                const float bv1 = __ldg(bias + e0 + eloc + q * 2 + 1);
                const float bv8_0 = __ldg(bias + e0 + eloc + 8 + q * 2);
                const float bv8_1 = __ldg(bias + e0 + eloc + 8 + q * 2 + 1);
                const uint32_t r0 = packh2(acc[i][2 * jp][0] + bv0, acc[i][2 * jp][1] + bv1);
                const uint32_t r1 = packh2(acc[i][2 * jp][2] + bv0, acc[i][2 * jp][3] + bv1);
                const uint32_t r2 =
                    packh2(acc[i][2 * jp + 1][0] + bv8_0, acc[i][2 * jp + 1][1] + bv8_1);
                const uint32_t r3 =
                    packh2(acc[i][2 * jp + 1][2] + bv8_0, acc[i][2 * jp + 1][3] + bv8_1);
                const int erow = eloc + (tt >> 1) * 8 + r;
                const int mcol = m0c + (tt & 1) * 8;
                stsm4t(sb + (uint32_t)(erow * SEP + mcol) * 2, r0, r1, r2, r3);
            }
        }
    }
    __syncthreads();
    {
        // thread tid streams e-row tid: 16 x (LDS.128 + STG.128), full sectors
        const uint4* srow = (const uint4*)(smem + (size_t)tid * SEP * 2);
        __half* gout = Cout + (size_t)b * E_ * S_ + (size_t)(e0 + tid) * S_ + s0;
#pragma unroll
        for (int k = 0; k < 16; k++) {
            const uint4 val = srow[k];
            *(uint4*)(gout + k * 8) = val;
        }
    }
}

// ------------------------------- Scan --------------------------------------

__device__ __forceinline__ float sigm(float x) { return 1.0f / (1.0f + __expf(-x)); }
__device__ __forceinline__ void step_cv(float gg, float hh, float& c, float& v) {
    const float z = sigm(gg);
    c = 1.0f - z;
    const float gl = (hh >= 0.f) ? (hh + 0.5f) : sigm(hh);
    v = z * gl;
}

// gh: (B,2H,S) half. Both modes emit token-major (B,S,H) via smem transpose:
// HALFOUT=true -> half (feeds GEMM1); HALFOUT=false -> f32 (final output).
template <bool HALFOUT>
__global__ __launch_bounds__(256) void scan_kernel(
    const __half* __restrict__ gh, void* __restrict__ outv)
{
    __shared__ float stg[2080];
    const int tid = threadIdx.x, w = tid >> 5, lane = tid & 31;
    const int gw = blockIdx.x * 8 + w;
    const int b = gw >> 10;
    const int h = gw & 1023;
    const int h0 = (blockIdx.x * 8) & 1023;

    const __half* gate = gh + ((size_t)b * E_ + h) * S_;
    const __half* hid = gate + (size_t)H_ * S_;

    float hprev = 0.5f;

    for (int iter = 0; iter < 8; ++iter) {
        const int sbase = iter * 512 + lane * 16;   // 16 halfs = 32B
        const uint4* g4 = (const uint4*)(gate + sbase);
        const uint4* h4 = (const uint4*)(hid + sbase);

        uint4 gu[2], hu[2];
        gu[0] = __ldg(g4); gu[1] = __ldg(g4 + 1);
        hu[0] = __ldg(h4); hu[1] = __ldg(h4 + 1);
        float gf[16], hf[16];
#pragma unroll
        for (int p = 0; p < 8; p++) {
            const float2 gg2 = __half22float2(((const __half2*)gu)[p]);
            const float2 hh2 = __half22float2(((const __half2*)hu)[p]);
            gf[2 * p] = gg2.x; gf[2 * p + 1] = gg2.y;
            hf[2 * p] = hh2.x; hf[2 * p + 1] = hh2.y;
        }

        float c[16], v[16];
        float C = 1.f, V = 0.f;
#pragma unroll
        for (int i = 0; i < 16; i++) {
            step_cv(gf[i], hf[i], c[i], v[i]);
            V = __fmaf_rn(c[i], V, v[i]);
            C *= c[i];
        }

        float Ci = C, Vi = V;
#pragma unroll
        for (int d = 1; d < 32; d <<= 1) {
            const float Cu = __shfl_up_sync(0xffffffffu, Ci, d);
            const float Vu = __shfl_up_sync(0xffffffffu, Vi, d);
            if (lane >= d) { Vi = __fmaf_rn(Ci, Vu, Vi); Ci *= Cu; }
        }
        const float C31 = __shfl_sync(0xffffffffu, Ci, 31);
        const float V31 = __shfl_sync(0xffffffffu, Vi, 31);
        const float Ce = __shfl_up_sync(0xffffffffu, Ci, 1);
        const float Ve = __shfl_up_sync(0xffffffffu, Vi, 1);
        float hcur = (lane == 0) ? hprev : __fmaf_rn(Ce, hprev, Ve);
        hprev = __fmaf_rn(C31, hprev, V31);

        float hv16[16];
#pragma unroll
        for (int i = 0; i < 16; i++) {
            hcur = __fmaf_rn(c[i], hcur, v[i]);
            hv16[i] = hcur;
        }

        // token-major emit via smem transpose: two sub-chunks of 8 steps
#pragma unroll
        for (int c2 = 0; c2 < 2; ++c2) {
#pragma unroll
            for (int t = 0; t < 8; t++) stg[lane * 65 + t * 8 + w] = hv16[c2 * 8 + t];
            __syncthreads();
            if (HALFOUT) {
                // 256 threads: (l,t) -> pack 8 floats -> one uint4 (16B) store
                const int t = tid & 7, l = tid >> 3;
                const int base = l * 65 + t * 8;
                uint4 o;
                o.x = packh2(stg[base + 0], stg[base + 1]);
                o.y = packh2(stg[base + 2], stg[base + 3]);
                o.z = packh2(stg[base + 4], stg[base + 5]);
                o.w = packh2(stg[base + 6], stg[base + 7]);
                const int s = iter * 512 + l * 16 + c2 * 8 + t;
                *(uint4*)((__half*)outv + ((size_t)b * S_ + s) * H_ + h0) = o;
            } else {
#pragma unroll
                for (int i = 0; i < 2; i++) {
                    const int f = i * 256 + tid;
                    const int half_ = f & 1, t = (f >> 1) & 7, l = f >> 4;
                    const int base = l * 65 + t * 8 + half_ * 4;
                    float4 o;
                    o.x = stg[base]; o.y = stg[base + 1];
                    o.z = stg[base + 2]; o.w = stg[base + 3];
                    const int s = iter * 512 + l * 16 + c2 * 8 + t;
                    *(float4*)((float*)outv + ((size_t)b * S_ + s) * H_ + h0 + half_ * 4) = o;
                }
            }
            __syncthreads();
        }
    }
}

// ------------------------------ Launch -------------------------------------

extern "C" void kernel_launch(void* const* d_in, const int* in_sizes, int n_in,
                              void* d_out, int out_size)
{
    (void)in_sizes; (void)n_in; (void)out_size;
    const float* x = (const float*)d_in[0];
    const float* W0 = (const float*)d_in[1];
    const float* b0 = (const float*)d_in[2];
    const float* W1 = (const float*)d_in[3];
    const float* b1 = (const float*)d_in[4];
    float* out = (float*)d_out;

    __half *gbuf, *h1h, *xh, *w0h, *w1h;
    cudaGetSymbolAddress((void**)&gbuf, g_gbuf);
    cudaGetSymbolAddress((void**)&h1h, g_h1h);
    cudaGetSymbolAddress((void**)&xh, g_xh);
    cudaGetSymbolAddress((void**)&w0h, g_w0h);
    cudaGetSymbolAddress((void**)&w1h, g_w1h);

    cudaFuncSetAttribute(gemm_kernel,
                         cudaFuncAttributeMaxDynamicSharedMemorySize, SMEM_GEMM);

    tohalf_kernel<<<(int)((size_t)M_ * K_ / 1024), 256>>>(x, xh);
    tohalf_kernel<<<(int)((size_t)E_ * K_ / 1024), 256>>>(W0, w0h);
    tohalf_kernel<<<(int)((size_t)E_ * K_ / 1024), 256>>>(W1, w1h);

    const dim3 gGrid(E_ / BN, M_ / BM);     // (16, 256)
    const int scanBlocks = (B_ * H_) / 8;   // 1024

    gemm_kernel<<<gGrid, 128, SMEM_GEMM>>>(xh, w0h, b0, gbuf);
    scan_kernel<true><<<scanBlocks, 256>>>(gbuf, h1h);
    gemm_kernel<<<gGrid, 128, SMEM_GEMM>>>(h1h, w1h, b1, gbuf);
    scan_kernel<false><<<scanBlocks, 256>>>(gbuf, out);
}

// round 14
// speedup vs baseline: 1.0443x; 1.0443x over previous
#include <cuda_runtime.h>
#include <cuda_fp16.h>
#include <cstdint>
#include <cstddef>

// ---------------------------------------------------------------------------
// MinGRU (2 layers): tohalf(x,W0,W1) -> GEMM0 -> scan0 -> GEMM1 -> scan1
// B=8, S=4096, D=H=1024, E=2H=2048, M=32768, K=1024.
// GEMM: fp16 mma.sync.m16n8k16 (f32 accum), CTA 128x128 / 4 warps (64x64 each),
//       BK=64, 3-stage cp.async, ldmatrix + xor swizzle, 2 CTAs/SM.
//       Epilogue: stmatrix.x4.trans -> [e][m] smem image -> coalesced STG.128.
// GEMM out: channel-major (B,2H,S) FP16. Scan: warp/channel single-pass
//       affine scan reading half2 (ldcs streaming); scan0 emits half (B,H,S)
//       feeding GEMM1 (ACH path); scan1 emits f32 (B,S,H) via smem transpose
//       with stcs streaming stores.
// ---------------------------------------------------------------------------

#define B_ 8
#define S_ 4096
#define K_ 1024
#define H_ 1024
#define E_ 2048
#define M_ (B_ * S_)

// scratch (no cudaMalloc allowed)
__device__ __half g_gbuf[(size_t)B_ * E_ * S_];    // 134 MB GEMM out (B,2H,S) half
__device__ __half g_h1h[(size_t)B_ * H_ * S_];     // 67 MB layer-0 h, half (B,H,S)
__device__ __half g_xh[(size_t)M_ * K_];           // 67 MB x in half
__device__ __half g_w0h[(size_t)E_ * K_];          // 4 MB
__device__ __half g_w1h[(size_t)E_ * K_];          // 4 MB

// ------------------------------ helpers ------------------------------------

__device__ __forceinline__ void cpasync16(uint32_t dst, const void* src) {
    asm volatile("cp.async.cg.shared.global [%0], [%1], 16;\n" ::"r"(dst), "l"(src));
}
__device__ __forceinline__ void cpcommit() { asm volatile("cp.async.commit_group;\n"); }
__device__ __forceinline__ void cpwait1() { asm volatile("cp.async.wait_group 1;\n"); }
__device__ __forceinline__ void cpwait0() { asm volatile("cp.async.wait_group 0;\n"); }

__device__ __forceinline__ void ldsm4(uint32_t* d, uint32_t addr) {
    asm volatile("ldmatrix.sync.aligned.m8n8.x4.shared.b16 {%0,%1,%2,%3}, [%4];"
                 : "=r"(d[0]), "=r"(d[1]), "=r"(d[2]), "=r"(d[3]) : "r"(addr));
}
__device__ __forceinline__ void ldsm4t(uint32_t* d, uint32_t addr) {
    asm volatile("ldmatrix.sync.aligned.m8n8.x4.trans.shared.b16 {%0,%1,%2,%3}, [%4];"
                 : "=r"(d[0]), "=r"(d[1]), "=r"(d[2]), "=r"(d[3]) : "r"(addr));
}
__device__ __forceinline__ void stsm4t(uint32_t addr, uint32_t r0, uint32_t r1,
                                       uint32_t r2, uint32_t r3) {
    asm volatile("stmatrix.sync.aligned.m8n8.x4.trans.shared.b16 [%0], {%1,%2,%3,%4};"
                 ::"r"(addr), "r"(r0), "r"(r1), "r"(r2), "r"(r3) : "memory");
}
__device__ __forceinline__ void mma_f16(float* c, const uint32_t* a, const uint32_t* b) {
    asm volatile(
        "mma.sync.aligned.m16n8k16.row.col.f32.f16.f16.f32 "
        "{%0,%1,%2,%3}, {%4,%5,%6,%7}, {%8,%9}, {%0,%1,%2,%3};\n"
        : "+f"(c[0]), "+f"(c[1]), "+f"(c[2]), "+f"(c[3])
        : "r"(a[0]), "r"(a[1]), "r"(a[2]), "r"(a[3]), "r"(b[0]), "r"(b[1]));
}
__device__ __forceinline__ uint32_t packh2(float a, float b) {
    const __half2 h = __floats2half2_rn(a, b);
    return *(const uint32_t*)&h;
}

// --------------------------- f32 -> f16 transform --------------------------

__global__ void tohalf_kernel(const float* __restrict__ in, __half* __restrict__ out) {
    const size_t i = ((size_t)blockIdx.x * 256 + threadIdx.x) * 4;
    const float4 v = *(const float4*)(in + i);
    uint2 u;
    u.x = packh2(v.x, v.y);
    u.y = packh2(v.z, v.w);
    *(uint2*)(out + i) = u;
}

// ------------------------------- GEMM --------------------------------------
// CTA 128(M) x 128(N), BK=64; 4 warps (2x2), warp tile 64x64; 2 CTAs/SM.
// smem (half): A stage 16KB, W stage 16KB, 3 stages = 96KB (epilogue reuses).
// Swizzle: 16B chunk c of row r stored at chunk c ^ (r & 7).

#define BM 128
#define BN 128
#define BK 64
#define NTT (K_ / BK)      // 16 k-tiles
#define ASTG 16384
#define WSTG 16384
#define SMEM_GEMM (3 * (ASTG + WSTG))   // 98304 B
#define SEP 136            // epilogue [e][m] row stride in halfs (272 B)

// ACH=false: A token-major (M,K) half. ACH=true: A channel-major (B,K,S) half.
template <bool ACH>
__global__ __launch_bounds__(128, 2) void gemm_kernel(
    const __half* __restrict__ A, const __half* __restrict__ W,
    const float* __restrict__ bias, __half* __restrict__ Cout)
{
    extern __shared__ char smem[];
    const uint32_t sb = (uint32_t)__cvta_generic_to_shared(smem);

    const int tid = threadIdx.x;
    const int warp = tid >> 5, lane = tid & 31;
    const int tt = lane >> 3, r = lane & 7;   // ldmatrix tile id / row-in-tile
    const int mw = (warp & 1) * 64;
    const int nw = (warp >> 1) * 64;

    const int m0 = blockIdx.y * BM;
    const int b = m0 >> 12;
    const int s0 = m0 & (S_ - 1);
    const int e0 = blockIdx.x * BN;

    const __half* Ablk;
    if (ACH) Ablk = A + (size_t)b * K_ * S_ + s0;   // + k*S_ + m_local
    else     Ablk = A + (size_t)m0 * K_;            // + m_local*K_ + k
    const __half* Wblk = W + (size_t)e0 * K_;

    auto loadTile = [&](int kt, int st) {
        const uint32_t aBase = sb + st * ASTG;
        const uint32_t wBase = sb + 3 * ASTG + st * WSTG;
#pragma unroll
        for (int it = 0; it < 8; ++it) {            // A: 1024 x 16B
            const int id = tid + it * 128;
            if (ACH) {
                const int rr = id >> 4, c = id & 15;    // 64 k-rows x 16 chunks
                cpasync16(aBase + rr * 256 + ((c ^ (rr & 7)) * 16),
                          Ablk + (size_t)(kt * BK + rr) * S_ + c * 8);
            } else {
                const int m = id >> 3, c = id & 7;      // 128 m-rows x 8 chunks
                cpasync16(aBase + m * 128 + ((c ^ (m & 7)) * 16),
                          Ablk + (size_t)m * K_ + kt * BK + c * 8);
            }
        }
#pragma unroll
        for (int it = 0; it < 8; ++it) {            // W: 1024 x 16B
            const int id = tid + it * 128;
            const int e = id >> 3, c = id & 7;
            cpasync16(wBase + e * 128 + ((c ^ (e & 7)) * 16),
                      Wblk + (size_t)e * K_ + kt * BK + c * 8);
        }
    };

    float acc[4][8][4];
#pragma unroll
    for (int i = 0; i < 4; i++)
#pragma unroll
        for (int j = 0; j < 8; j++)
#pragma unroll
            for (int x = 0; x < 4; x++) acc[i][j][x] = 0.f;

    loadTile(0, 0); cpcommit();
    loadTile(1, 1); cpcommit();

    for (int t = 0; t < NTT; ++t) {
        if (t + 1 < NTT) cpwait1(); else cpwait0();   // tile t fully landed
        __syncthreads();
        if (t + 2 < NTT) { loadTile(t + 2, (t + 2) % 3); cpcommit(); }

        const uint32_t aB = sb + (t % 3) * ASTG;
        const uint32_t wB = sb + 3 * ASTG + (t % 3) * WSTG;

#pragma unroll
        for (int s = 0; s < 4; ++s) {               // 4 x k16 per tile
            uint32_t af[4][4], bf[4][4];
#pragma unroll
            for (int i = 0; i < 4; i++) {
                if (ACH) {
                    const int krow = s * 16 + (tt >> 1) * 8 + r;
                    const int mch = ((mw + i * 16) >> 3) + (tt & 1);
                    ldsm4t(af[i], aB + krow * 256 + ((mch ^ r) * 16));
                } else {
                    const int row = mw + i * 16 + (tt & 1) * 8 + r;
                    const int kch = s * 2 + (tt >> 1);
                    ldsm4(af[i], aB + row * 128 + ((kch ^ r) * 16));
                }
            }
#pragma unroll
            for (int jp = 0; jp < 4; jp++) {
                const int e = nw + jp * 16 + (tt >> 1) * 8 + r;
                const int kch = s * 2 + (tt & 1);
                ldsm4(bf[jp], wB + e * 128 + ((kch ^ r) * 16));
            }
#pragma unroll
            for (int i = 0; i < 4; i++)
#pragma unroll
                for (int j = 0; j < 8; j++)
                    mma_f16(acc[i][j], af[i], &bf[j >> 1][(j & 1) * 2]);
        }
    }

    // ---- epilogue: stmatrix.x4.trans -> [e][m] smem image -> STG.128 ----
    __syncthreads();   // mainloop smem stages no longer needed; reuse for image
    {
        const int q = lane & 3;
#pragma unroll
        for (int i = 0; i < 4; i++) {
            const int m0c = mw + i * 16;
#pragma unroll
            for (int jp = 0; jp < 4; jp++) {
                const int eloc = nw + jp * 16;
                const float bv0 = __ldg(bias + e0 + eloc + q * 2);
                const float bv1 = __ldg(bias + e0 + eloc + q * 2 + 1);
                const float bv8_0 = __ldg(bias + e0 + eloc + 8 + q * 2);
                const float bv8_1 = __ldg(bias + e0 + eloc + 8 + q * 2 + 1);
                const uint32_t r0 = packh2(acc[i][2 * jp][0] + bv0, acc[i][2 * jp][1] + bv1);
                const uint32_t r1 = packh2(acc[i][2 * jp][2] + bv0, acc[i][2 * jp][3] + bv1);
                const uint32_t r2 =
                    packh2(acc[i][2 * jp + 1][0] + bv8_0, acc[i][2 * jp + 1][1] + bv8_1);
                const uint32_t r3 =
                    packh2(acc[i][2 * jp + 1][2] + bv8_0, acc[i][2 * jp + 1][3] + bv8_1);
                const int erow = eloc + (tt >> 1) * 8 + r;
                const int mcol = m0c + (tt & 1) * 8;
                stsm4t(sb + (uint32_t)(erow * SEP + mcol) * 2, r0, r1, r2, r3);
            }
        }
    }
    __syncthreads();
    {
        // thread tid streams e-row tid: 16 x (LDS.128 + STG.128), full sectors
        const uint4* srow = (const uint4*)(smem + (size_t)tid * SEP * 2);
        __half* gout = Cout + (size_t)b * E_ * S_ + (size_t)(e0 + tid) * S_ + s0;
#pragma unroll
        for (int k = 0; k < 16; k++) {
            const uint4 val = srow[k];
            *(uint4*)(gout + k * 8) = val;
        }
    }
}

// ------------------------------- Scan --------------------------------------

__device__ __forceinline__ float sigm(float x) { return 1.0f / (1.0f + __expf(-x)); }
__device__ __forceinline__ void step_cv(float gg, float hh, float& c, float& v) {
    const float z = sigm(gg);
    c = 1.0f - z;
    const float gl = (hh >= 0.f) ? (hh + 0.5f) : sigm(hh);
    v = z * gl;
}

// gh: (B,2H,S) half, read with ldcs (single-use stream).
// TOKOUT=false -> half (B,H,S) (feeds GEMM1, cached);
// TOKOUT=true -> f32 (B,S,H) via smem transpose, stcs streaming stores.
template <bool TOKOUT>
__global__ __launch_bounds__(256) void scan_kernel(
    const __half* __restrict__ gh, void* __restrict__ outv)
{
    __shared__ float stg[2080];
    const int tid = threadIdx.x, w = tid >> 5, lane = tid & 31;
    const int gw = blockIdx.x * 8 + w;
    const int b = gw >> 10;
    const int h = gw & 1023;
    const int h0 = (blockIdx.x * 8) & 1023;

    const __half* gate = gh + ((size_t)b * E_ + h) * S_;
    const __half* hid = gate + (size_t)H_ * S_;

    float hprev = 0.5f;

    for (int iter = 0; iter < 8; ++iter) {
        const int sbase = iter * 512 + lane * 16;   // 16 halfs = 32B
        const uint4* g4 = (const uint4*)(gate + sbase);
        const uint4* h4 = (const uint4*)(hid + sbase);

        uint4 gu[2], hu[2];
        gu[0] = __ldcs(g4); gu[1] = __ldcs(g4 + 1);
        hu[0] = __ldcs(h4); hu[1] = __ldcs(h4 + 1);
        float gf[16], hf[16];
#pragma unroll
        for (int p = 0; p < 8; p++) {
            const float2 gg2 = __half22float2(((const __half2*)gu)[p]);
            const float2 hh2 = __half22float2(((const __half2*)hu)[p]);
            gf[2 * p] = gg2.x; gf[2 * p + 1] = gg2.y;
            hf[2 * p] = hh2.x; hf[2 * p + 1] = hh2.y;
        }

        float c[16], v[16];
        float C = 1.f, V = 0.f;
#pragma unroll
        for (int i = 0; i < 16; i++) {
            step_cv(gf[i], hf[i], c[i], v[i]);
            V = __fmaf_rn(c[i], V, v[i]);
            C *= c[i];
        }

        float Ci = C, Vi = V;
#pragma unroll
        for (int d = 1; d < 32; d <<= 1) {
            const float Cu = __shfl_up_sync(0xffffffffu, Ci, d);
            const float Vu = __shfl_up_sync(0xffffffffu, Vi, d);
            if (lane >= d) { Vi = __fmaf_rn(Ci, Vu, Vi); Ci *= Cu; }
        }
        const float C31 = __shfl_sync(0xffffffffu, Ci, 31);
        const float V31 = __shfl_sync(0xffffffffu, Vi, 31);
        const float Ce = __shfl_up_sync(0xffffffffu, Ci, 1);
        const float Ve = __shfl_up_sync(0xffffffffu, Vi, 1);
        float hcur = (lane == 0) ? hprev : __fmaf_rn(Ce, hprev, Ve);
        hprev = __fmaf_rn(C31, hprev, V31);

        float hv16[16];
#pragma unroll
        for (int i = 0; i < 16; i++) {
            hcur = __fmaf_rn(c[i], hcur, v[i]);
            hv16[i] = hcur;
        }

        if (!TOKOUT) {
            __half* outh = (__half*)outv + (size_t)b * H_ * S_ + (size_t)h * S_ + sbase;
            uint32_t u[8];
#pragma unroll
            for (int i = 0; i < 8; i++) u[i] = packh2(hv16[2 * i], hv16[2 * i + 1]);
            ((uint4*)outh)[0] = make_uint4(u[0], u[1], u[2], u[3]);
            ((uint4*)outh)[1] = make_uint4(u[4], u[5], u[6], u[7]);
        } else {
            float* out = (float*)outv;
#pragma unroll
            for (int c2 = 0; c2 < 2; ++c2) {
#pragma unroll
                for (int t = 0; t < 8; t++) stg[lane * 65 + t * 8 + w] = hv16[c2 * 8 + t];
                __syncthreads();
#pragma unroll
                for (int i = 0; i < 2; i++) {
                    const int f = i * 256 + tid;
                    const int half_ = f & 1, t = (f >> 1) & 7, l = f >> 4;
                    const int base = l * 65 + t * 8 + half_ * 4;
                    float4 o;
                    o.x = stg[base]; o.y = stg[base + 1];
                    o.z = stg[base + 2]; o.w = stg[base + 3];
                    const int s = iter * 512 + l * 16 + c2 * 8 + t;
                    __stcs((float4*)(out + ((size_t)b * S_ + s) * H_ + h0 + half_ * 4), o);
                }
                __syncthreads();
            }
        }
    }
}

// ------------------------------ Launch -------------------------------------

extern "C" void kernel_launch(void* const* d_in, const int* in_sizes, int n_in,
                              void* d_out, int out_size)
{
    (void)in_sizes; (void)n_in; (void)out_size;
    const float* x = (const float*)d_in[0];
    const float* W0 = (const float*)d_in[1];
    const float* b0 = (const float*)d_in[2];
    const float* W1 = (const float*)d_in[3];
    const float* b1 = (const float*)d_in[4];
    float* out = (float*)d_out;

    __half *gbuf, *h1h, *xh, *w0h, *w1h;
    cudaGetSymbolAddress((void**)&gbuf, g_gbuf);
    cudaGetSymbolAddress((void**)&h1h, g_h1h);
    cudaGetSymbolAddress((void**)&xh, g_xh);
    cudaGetSymbolAddress((void**)&w0h, g_w0h);
    cudaGetSymbolAddress((void**)&w1h, g_w1h);

    cudaFuncSetAttribute(gemm_kernel<false>,
                         cudaFuncAttributeMaxDynamicSharedMemorySize, SMEM_GEMM);
    cudaFuncSetAttribute(gemm_kernel<true>,
                         cudaFuncAttributeMaxDynamicSharedMemorySize, SMEM_GEMM);

    tohalf_kernel<<<(int)((size_t)M_ * K_ / 1024), 256>>>(x, xh);
    tohalf_kernel<<<(int)((size_t)E_ * K_ / 1024), 256>>>(W0, w0h);
    tohalf_kernel<<<(int)((size_t)E_ * K_ / 1024), 256>>>(W1, w1h);

    const dim3 gGrid(E_ / BN, M_ / BM);     // (16, 256)
    const int scanBlocks = (B_ * H_) / 8;   // 1024

    gemm_kernel<false><<<gGrid, 128, SMEM_GEMM>>>(xh, w0h, b0, gbuf);
    scan_kernel<false><<<scanBlocks, 256>>>(gbuf, h1h);
    gemm_kernel<true><<<gGrid, 128, SMEM_GEMM>>>(h1h, w1h, b1, gbuf);
    scan_kernel<true><<<scanBlocks, 256>>>(gbuf, out);
}

// round 15
// speedup vs baseline: 1.0722x; 1.0267x over previous
#include <cuda_runtime.h>
#include <cuda_fp16.h>
#include <cstdint>
#include <cstddef>

// ---------------------------------------------------------------------------
// MinGRU (2 layers), batch-split dual-stream pipeline:
//   main:  T(W0) T(W1) T(x,A) | G0(A) s0(A) G1(A) s1(A)
//   s2:    (wait)     T(x,B)  | G0(B) s0(B) G1(B) s1(B)   (fork/join via events)
// Kernels identical to the proven 842us version (R14): fp16 mma.sync GEMM
// 128x128/BK64/3-stage/2 CTAs/SM with stmatrix epilogue; single-pass affine
// scans with ldcs/stcs streaming.
// ---------------------------------------------------------------------------

#define B_ 8
#define S_ 4096
#define K_ 1024
#define H_ 1024
#define E_ 2048
#define M_ (B_ * S_)
#define BH 4                 // batches per stream set

// scratch (no cudaMalloc allowed)
__device__ __half g_gbuf[(size_t)B_ * E_ * S_];    // 134 MB GEMM out (B,2H,S) half
__device__ __half g_h1h[(size_t)B_ * H_ * S_];     // 67 MB layer-0 h, half (B,H,S)
__device__ __half g_xh[(size_t)M_ * K_];           // 67 MB x in half
__device__ __half g_w0h[(size_t)E_ * K_];          // 4 MB
__device__ __half g_w1h[(size_t)E_ * K_];          // 4 MB

// ------------------------------ helpers ------------------------------------

__device__ __forceinline__ void cpasync16(uint32_t dst, const void* src) {
    asm volatile("cp.async.cg.shared.global [%0], [%1], 16;\n" ::"r"(dst), "l"(src));
}
__device__ __forceinline__ void cpcommit() { asm volatile("cp.async.commit_group;\n"); }
__device__ __forceinline__ void cpwait1() { asm volatile("cp.async.wait_group 1;\n"); }
__device__ __forceinline__ void cpwait0() { asm volatile("cp.async.wait_group 0;\n"); }

__device__ __forceinline__ void ldsm4(uint32_t* d, uint32_t addr) {
    asm volatile("ldmatrix.sync.aligned.m8n8.x4.shared.b16 {%0,%1,%2,%3}, [%4];"
                 : "=r"(d[0]), "=r"(d[1]), "=r"(d[2]), "=r"(d[3]) : "r"(addr));
}
__device__ __forceinline__ void ldsm4t(uint32_t* d, uint32_t addr) {
    asm volatile("ldmatrix.sync.aligned.m8n8.x4.trans.shared.b16 {%0,%1,%2,%3}, [%4];"
                 : "=r"(d[0]), "=r"(d[1]), "=r"(d[2]), "=r"(d[3]) : "r"(addr));
}
__device__ __forceinline__ void stsm4t(uint32_t addr, uint32_t r0, uint32_t r1,
                                       uint32_t r2, uint32_t r3) {
    asm volatile("stmatrix.sync.aligned.m8n8.x4.trans.shared.b16 [%0], {%1,%2,%3,%4};"
                 ::"r"(addr), "r"(r0), "r"(r1), "r"(r2), "r"(r3) : "memory");
}
__device__ __forceinline__ void mma_f16(float* c, const uint32_t* a, const uint32_t* b) {
    asm volatile(
        "mma.sync.aligned.m16n8k16.row.col.f32.f16.f16.f32 "
        "{%0,%1,%2,%3}, {%4,%5,%6,%7}, {%8,%9}, {%0,%1,%2,%3};\n"
        : "+f"(c[0]), "+f"(c[1]), "+f"(c[2]), "+f"(c[3])
        : "r"(a[0]), "r"(a[1]), "r"(a[2]), "r"(a[3]), "r"(b[0]), "r"(b[1]));
}
__device__ __forceinline__ uint32_t packh2(float a, float b) {
    const __half2 h = __floats2half2_rn(a, b);
    return *(const uint32_t*)&h;
}

// --------------------------- f32 -> f16 transform --------------------------

__global__ void tohalf_kernel(const float* __restrict__ in, __half* __restrict__ out) {
    const size_t i = ((size_t)blockIdx.x * 256 + threadIdx.x) * 4;
    const float4 v = *(const float4*)(in + i);
    uint2 u;
    u.x = packh2(v.x, v.y);
    u.y = packh2(v.z, v.w);
    *(uint2*)(out + i) = u;
}

// ------------------------------- GEMM --------------------------------------
// CTA 128(M) x 128(N), BK=64; 4 warps (2x2), warp tile 64x64; 2 CTAs/SM.
// smem (half): A stage 16KB, W stage 16KB, 3 stages = 96KB (epilogue reuses).
// Swizzle: 16B chunk c of row r stored at chunk c ^ (r & 7).
// Grid y covers BH batches; all pointers pre-offset to the batch set base.

#define BM 128
#define BN 128
#define BK 64
#define NTT (K_ / BK)      // 16 k-tiles
#define ASTG 16384
#define WSTG 16384
#define SMEM_GEMM (3 * (ASTG + WSTG))   // 98304 B
#define SEP 136            // epilogue [e][m] row stride in halfs (272 B)

// ACH=false: A token-major (M,K) half. ACH=true: A channel-major (B,K,S) half.
template <bool ACH>
__global__ __launch_bounds__(128, 2) void gemm_kernel(
    const __half* __restrict__ A, const __half* __restrict__ W,
    const float* __restrict__ bias, __half* __restrict__ Cout)
{
    extern __shared__ char smem[];
    const uint32_t sb = (uint32_t)__cvta_generic_to_shared(smem);

    const int tid = threadIdx.x;
    const int warp = tid >> 5, lane = tid & 31;
    const int tt = lane >> 3, r = lane & 7;   // ldmatrix tile id / row-in-tile
    const int mw = (warp & 1) * 64;
    const int nw = (warp >> 1) * 64;

    const int m0 = blockIdx.y * BM;
    const int b = m0 >> 12;          // batch relative to set base
    const int s0 = m0 & (S_ - 1);
    const int e0 = blockIdx.x * BN;

    const __half* Ablk;
    if (ACH) Ablk = A + (size_t)b * K_ * S_ + s0;   // + k*S_ + m_local
    else     Ablk = A + (size_t)m0 * K_;            // + m_local*K_ + k
    const __half* Wblk = W + (size_t)e0 * K_;

    auto loadTile = [&](int kt, int st) {
        const uint32_t aBase = sb + st * ASTG;
        const uint32_t wBase = sb + 3 * ASTG + st * WSTG;
#pragma unroll
        for (int it = 0; it < 8; ++it) {            // A: 1024 x 16B
            const int id = tid + it * 128;
            if (ACH) {
                const int rr = id >> 4, c = id & 15;    // 64 k-rows x 16 chunks
                cpasync16(aBase + rr * 256 + ((c ^ (rr & 7)) * 16),
                          Ablk + (size_t)(kt * BK + rr) * S_ + c * 8);
            } else {
                const int m = id >> 3, c = id & 7;      // 128 m-rows x 8 chunks
                cpasync16(aBase + m * 128 + ((c ^ (m & 7)) * 16),
                          Ablk + (size_t)m * K_ + kt * BK + c * 8);
            }
        }
#pragma unroll
        for (int it = 0; it < 8; ++it) {            // W: 1024 x 16B
            const int id = tid + it * 128;
            const int e = id >> 3, c = id & 7;
            cpasync16(wBase + e * 128 + ((c ^ (e & 7)) * 16),
                      Wblk + (size_t)e * K_ + kt * BK + c * 8);
        }
    };

    float acc[4][8][4];
#pragma unroll
    for (int i = 0; i < 4; i++)
#pragma unroll
        for (int j = 0; j < 8; j++)
#pragma unroll
            for (int x = 0; x < 4; x++) acc[i][j][x] = 0.f;

    loadTile(0, 0); cpcommit();
    loadTile(1, 1); cpcommit();

    for (int t = 0; t < NTT; ++t) {
        if (t + 1 < NTT) cpwait1(); else cpwait0();   // tile t fully landed
        __syncthreads();
        if (t + 2 < NTT) { loadTile(t + 2, (t + 2) % 3); cpcommit(); }

        const uint32_t aB = sb + (t % 3) * ASTG;
        const uint32_t wB = sb + 3 * ASTG + (t % 3) * WSTG;

#pragma unroll
        for (int s = 0; s < 4; ++s) {               // 4 x k16 per tile
            uint32_t af[4][4], bf[4][4];
#pragma unroll
            for (int i = 0; i < 4; i++) {
                if (ACH) {
                    const int krow = s * 16 + (tt >> 1) * 8 + r;
                    const int mch = ((mw + i * 16) >> 3) + (tt & 1);
                    ldsm4t(af[i], aB + krow * 256 + ((mch ^ r) * 16));
                } else {
                    const int row = mw + i * 16 + (tt & 1) * 8 + r;
                    const int kch = s * 2 + (tt >> 1);
                    ldsm4(af[i], aB + row * 128 + ((kch ^ r) * 16));
                }
            }
#pragma unroll
            for (int jp = 0; jp < 4; jp++) {
                const int e = nw + jp * 16 + (tt >> 1) * 8 + r;
                const int kch = s * 2 + (tt & 1);
                ldsm4(bf[jp], wB + e * 128 + ((kch ^ r) * 16));
            }
#pragma unroll
            for (int i = 0; i < 4; i++)
#pragma unroll
                for (int j = 0; j < 8; j++)
                    mma_f16(acc[i][j], af[i], &bf[j >> 1][(j & 1) * 2]);
        }
    }

    // ---- epilogue: stmatrix.x4.trans -> [e][m] smem image -> STG.128 ----
    __syncthreads();   // mainloop smem stages no longer needed; reuse for image
    {
        const int q = lane & 3;
#pragma unroll
        for (int i = 0; i < 4; i++) {
            const int m0c = mw + i * 16;
#pragma unroll
            for (int jp = 0; jp < 4; jp++) {
                const int eloc = nw + jp * 16;
                const float bv0 = __ldg(bias + e0 + eloc + q * 2);
                const float bv1 = __ldg(bias + e0 + eloc + q * 2 + 1);
                const float bv8_0 = __ldg(bias + e0 + eloc + 8 + q * 2);
                const float bv8_1 = __ldg(bias + e0 + eloc + 8 + q * 2 + 1);
                const uint32_t r0 = packh2(acc[i][2 * jp][0] + bv0, acc[i][2 * jp][1] + bv1);
                const uint32_t r1 = packh2(acc[i][2 * jp][2] + bv0, acc[i][2 * jp][3] + bv1);
                const uint32_t r2 =
                    packh2(acc[i][2 * jp + 1][0] + bv8_0, acc[i][2 * jp + 1][1] + bv8_1);
                const uint32_t r3 =
                    packh2(acc[i][2 * jp + 1][2] + bv8_0, acc[i][2 * jp + 1][3] + bv8_1);
                const int erow = eloc + (tt >> 1) * 8 + r;
                const int mcol = m0c + (tt & 1) * 8;
                stsm4t(sb + (uint32_t)(erow * SEP + mcol) * 2, r0, r1, r2, r3);
            }
        }
    }
    __syncthreads();
    {
        // thread tid streams e-row tid: 16 x (LDS.128 + STG.128), full sectors
        const uint4* srow = (const uint4*)(smem + (size_t)tid * SEP * 2);
        __half* gout = Cout + (size_t)b * E_ * S_ + (size_t)(e0 + tid) * S_ + s0;
#pragma unroll
        for (int k = 0; k < 16; k++) {
            const uint4 val = srow[k];
            *(uint4*)(gout + k * 8) = val;
        }
    }
}

// ------------------------------- Scan --------------------------------------

__device__ __forceinline__ float sigm(float x) { return 1.0f / (1.0f + __expf(-x)); }
__device__ __forceinline__ void step_cv(float gg, float hh, float& c, float& v) {
    const float z = sigm(gg);
    c = 1.0f - z;
    const float gl = (hh >= 0.f) ? (hh + 0.5f) : sigm(hh);
    v = z * gl;
}

// gh: (BH,2H,S) half (set base), ldcs streaming reads.
// TOKOUT=false -> half (BH,H,S) (feeds GEMM1); TOKOUT=true -> f32 (BH,S,H)
// via smem transpose with stcs streaming stores.
template <bool TOKOUT>
__global__ __launch_bounds__(256) void scan_kernel(
    const __half* __restrict__ gh, void* __restrict__ outv)
{
    __shared__ float stg[2080];
    const int tid = threadIdx.x, w = tid >> 5, lane = tid & 31;
    const int gw = blockIdx.x * 8 + w;
    const int b = gw >> 10;          // batch relative to set base
    const int h = gw & 1023;
    const int h0 = (blockIdx.x * 8) & 1023;

    const __half* gate = gh + ((size_t)b * E_ + h) * S_;
    const __half* hid = gate + (size_t)H_ * S_;

    float hprev = 0.5f;

    for (int iter = 0; iter < 8; ++iter) {
        const int sbase = iter * 512 + lane * 16;   // 16 halfs = 32B
        const uint4* g4 = (const uint4*)(gate + sbase);
        const uint4* h4 = (const uint4*)(hid + sbase);

        uint4 gu[2], hu[2];
        gu[0] = __ldcs(g4); gu[1] = __ldcs(g4 + 1);
        hu[0] = __ldcs(h4); hu[1] = __ldcs(h4 + 1);
        float gf[16], hf[16];
#pragma unroll
        for (int p = 0; p < 8; p++) {
            const float2 gg2 = __half22float2(((const __half2*)gu)[p]);
            const float2 hh2 = __half22float2(((const __half2*)hu)[p]);
            gf[2 * p] = gg2.x; gf[2 * p + 1] = gg2.y;
            hf[2 * p] = hh2.x; hf[2 * p + 1] = hh2.y;
        }

        float c[16], v[16];
        float C = 1.f, V = 0.f;
#pragma unroll
        for (int i = 0; i < 16; i++) {
            step_cv(gf[i], hf[i], c[i], v[i]);
            V = __fmaf_rn(c[i], V, v[i]);
            C *= c[i];
        }

        float Ci = C, Vi = V;
#pragma unroll
        for (int d = 1; d < 32; d <<= 1) {
            const float Cu = __shfl_up_sync(0xffffffffu, Ci, d);
            const float Vu = __shfl_up_sync(0xffffffffu, Vi, d);
            if (lane >= d) { Vi = __fmaf_rn(Ci, Vu, Vi); Ci *= Cu; }
        }
        const float C31 = __shfl_sync(0xffffffffu, Ci, 31);
        const float V31 = __shfl_sync(0xffffffffu, Vi, 31);
        const float Ce = __shfl_up_sync(0xffffffffu, Ci, 1);
        const float Ve = __shfl_up_sync(0xffffffffu, Vi, 1);
        float hcur = (lane == 0) ? hprev : __fmaf_rn(Ce, hprev, Ve);
        hprev = __fmaf_rn(C31, hprev, V31);

        float hv16[16];
#pragma unroll
        for (int i = 0; i < 16; i++) {
            hcur = __fmaf_rn(c[i], hcur, v[i]);
            hv16[i] = hcur;
        }

        if (!TOKOUT) {
            __half* outh = (__half*)outv + (size_t)b * H_ * S_ + (size_t)h * S_ + sbase;
            uint32_t u[8];
#pragma unroll
            for (int i = 0; i < 8; i++) u[i] = packh2(hv16[2 * i], hv16[2 * i + 1]);
            ((uint4*)outh)[0] = make_uint4(u[0], u[1], u[2], u[3]);
            ((uint4*)outh)[1] = make_uint4(u[4], u[5], u[6], u[7]);
        } else {
            float* out = (float*)outv;
#pragma unroll
            for (int c2 = 0; c2 < 2; ++c2) {
#pragma unroll
                for (int t = 0; t < 8; t++) stg[lane * 65 + t * 8 + w] = hv16[c2 * 8 + t];
                __syncthreads();
#pragma unroll
                for (int i = 0; i < 2; i++) {
                    const int f = i * 256 + tid;
                    const int half_ = f & 1, t = (f >> 1) & 7, l = f >> 4;
                    const int base = l * 65 + t * 8 + half_ * 4;
                    float4 o;
                    o.x = stg[base]; o.y = stg[base + 1];
                    o.z = stg[base + 2]; o.w = stg[base + 3];
                    const int s = iter * 512 + l * 16 + c2 * 8 + t;
                    __stcs((float4*)(out + ((size_t)b * S_ + s) * H_ + h0 + half_ * 4), o);
                }
                __syncthreads();
            }
        }
    }
}

// ------------------------------ Launch -------------------------------------

extern "C" void kernel_launch(void* const* d_in, const int* in_sizes, int n_in,
                              void* d_out, int out_size)
{
    (void)in_sizes; (void)n_in; (void)out_size;
    const float* x = (const float*)d_in[0];
    const float* W0 = (const float*)d_in[1];
    const float* b0 = (const float*)d_in[2];
    const float* W1 = (const float*)d_in[3];
    const float* b1 = (const float*)d_in[4];
    float* out = (float*)d_out;

    __half *gbuf, *h1h, *xh, *w0h, *w1h;
    cudaGetSymbolAddress((void**)&gbuf, g_gbuf);
    cudaGetSymbolAddress((void**)&h1h, g_h1h);
    cudaGetSymbolAddress((void**)&xh, g_xh);
    cudaGetSymbolAddress((void**)&w0h, g_w0h);
    cudaGetSymbolAddress((void**)&w1h, g_w1h);

    cudaFuncSetAttribute(gemm_kernel<false>,
                         cudaFuncAttributeMaxDynamicSharedMemorySize, SMEM_GEMM);
    cudaFuncSetAttribute(gemm_kernel<true>,
                         cudaFuncAttributeMaxDynamicSharedMemorySize, SMEM_GEMM);

    // One-time stream/event setup (outside capture: first call is the
    // correctness run). Same DAG every call -> deterministic. Fallback to
    // legacy-stream serial execution if creation fails.
    static cudaStream_t s2 = nullptr;
    static cudaEvent_t evF = nullptr, evJ = nullptr;
    static bool init_done = false;
    if (!init_done) {
        if (cudaStreamCreateWithFlags(&s2, cudaStreamNonBlocking) != cudaSuccess)
            s2 = nullptr;
        if (s2) {
            if (cudaEventCreateWithFlags(&evF, cudaEventDisableTiming) != cudaSuccess ||
                cudaEventCreateWithFlags(&evJ, cudaEventDisableTiming) != cudaSuccess) {
                s2 = nullptr;
            }
        }
        init_done = true;
    }

    // per-set sizes / offsets (BH = 4 batches per set)
    const size_t xOffF = (size_t)BH * S_ * K_;        // floats into x
    const size_t xOffH = xOffF;                       // halfs into xh
    const size_t gOff = (size_t)BH * E_ * S_;         // halfs into gbuf
    const size_t hOff = (size_t)BH * H_ * S_;         // halfs into h1h
    const size_t oOff = (size_t)BH * S_ * H_;         // floats into out

    const dim3 gGrid(E_ / BN, BH * S_ / BM);          // (16, 128) per set
    const int scanBlocks = (BH * H_) / 8;             // 512 per set
    const int xBlocks = (int)(xOffF / 1024);          // 16384 per set

    // shared W transforms on main stream (needed by both sets)
    tohalf_kernel<<<(int)((size_t)E_ * K_ / 1024), 256>>>(W0, w0h);
    tohalf_kernel<<<(int)((size_t)E_ * K_ / 1024), 256>>>(W1, w1h);
    // set A x-transform on main stream
    tohalf_kernel<<<xBlocks, 256>>>(x, xh);

    cudaStream_t sB = s2 ? s2 : (cudaStream_t)0;
    if (s2) {
        cudaEventRecord(evF, 0);          // after W transforms (+A xform queued)
        cudaStreamWaitEvent(s2, evF, 0);  // fork
    }

    // ---- set B chain (stream sB) ----
    tohalf_kernel<<<xBlocks, 256, 0, sB>>>(x + xOffF, xh + xOffH);
    gemm_kernel<false><<<gGrid, 128, SMEM_GEMM, sB>>>(xh + xOffH, w0h, b0, gbuf + gOff);
    scan_kernel<false><<<scanBlocks, 256, 0, sB>>>(gbuf + gOff, h1h + hOff);
    gemm_kernel<true><<<gGrid, 128, SMEM_GEMM, sB>>>(h1h + hOff, w1h, b1, gbuf + gOff);
    scan_kernel<true><<<scanBlocks, 256, 0, sB>>>(gbuf + gOff, out + oOff);

    // ---- set A chain (main stream) ----
    gemm_kernel<false><<<gGrid, 128, SMEM_GEMM>>>(xh, w0h, b0, gbuf);
    scan_kernel<false><<<scanBlocks, 256>>>(gbuf, h1h);
    gemm_kernel<true><<<gGrid, 128, SMEM_GEMM>>>(h1h, w1h, b1, gbuf);
    scan_kernel<true><<<scanBlocks, 256>>>(gbuf, out);

    if (s2) {
        cudaEventRecord(evJ, s2);         // join
        cudaStreamWaitEvent(0, evJ, 0);
    }
}